// round 3
// baseline (speedup 1.0000x reference)
#include <cuda_runtime.h>
#include <cstdint>

// Problem constants (shapes fixed by reference setup_inputs).
#define LD 512      // decoder length (M)
#define LE 2048     // encoder length (N)
#define DD 512      // feature dim (K)

// GEMM tiling — BK=16 so the DOUBLE-buffered tiles fit the 48KB static smem cap:
// 2 stages * 16 k * 132 floats * 4B * 2 arrays = 33,792 B < 49,152 B.
#define BM 128
#define BN 128
#define BK 16
#define BMP (BM + 4)   // smem row padding (132 % 4 == 0 keeps 16B alignment)
#define BNP (BN + 4)
#define NKT (DD / BK)  // 32 k-tiles

typedef unsigned long long ull;

__device__ __forceinline__ void fma2(ull& d, ull a, ull b) {
    // packed f32x2 FMA: d.lo += a.lo*b.lo ; d.hi += a.hi*b.hi (true FMA per lane)
    asm("fma.rn.f32x2 %0, %1, %2, %0;" : "+l"(d) : "l"(a), "l"(b));
}

__device__ __forceinline__ ull splat2(float x) {
    ull r;
    asm("mov.b64 %0, {%1, %1};" : "=l"(r) : "f"(x));
    return r;
}

__device__ __forceinline__ float lo32(ull v) { return __uint_as_float((unsigned)v); }
__device__ __forceinline__ float hi32(ull v) { return __uint_as_float((unsigned)(v >> 32)); }

// scores[b, m, n] = sum_k dec[b, m, k] * enc[b, n, k]   (NT gemm, both K-major)
__global__ __launch_bounds__(256, 2)
void gemm_nt_kernel(const float* __restrict__ A,   // [B, LD, DD]
                    const float* __restrict__ Bm,  // [B, LE, DD]
                    float* __restrict__ C)         // [B, LD, LE]
{
    const int b  = blockIdx.z;
    const int m0 = blockIdx.y * BM;
    const int n0 = blockIdx.x * BN;

    const float* Ab = A  + (size_t)b * LD * DD + (size_t)m0 * DD;
    const float* Bb = Bm + (size_t)b * LE * DD + (size_t)n0 * DD;
    float*       Cb = C  + (size_t)b * LD * LE;

    __shared__ float As[2][BK][BMP];  // transposed: As[s][k][m]
    __shared__ float Bs[2][BK][BNP];  // transposed: Bs[s][k][n]

    const int tid = threadIdx.x;      // 256 threads
    // global->smem load mapping: 128 rows x 16 k per tile; thread loads 2x float4
    // per matrix. lr: row within 64-row pass, lk: k offset.
    const int lr = tid >> 2;          // 0..63
    const int lk = (tid & 3) * 4;     // 0,4,8,12
    // compute mapping: 16x16 thread grid, 8x8 micro-tile
    const int tr = (tid >> 4) * 8;    // row base 0..120
    const int tc = (tid & 15) * 8;    // col base 0..120

    ull acc[4][8];                    // row-pairs x 8 cols, packed f32x2
#pragma unroll
    for (int i = 0; i < 4; i++)
#pragma unroll
        for (int j = 0; j < 8; j++) acc[i][j] = 0ull;

    // ---- prologue: load tile 0 into buffer 0 ----
#pragma unroll
    for (int pass = 0; pass < 2; pass++) {
        const int r = lr + pass * 64;
        const float4 a4 = *reinterpret_cast<const float4*>(&Ab[(size_t)r * DD + lk]);
        As[0][lk + 0][r] = a4.x;
        As[0][lk + 1][r] = a4.y;
        As[0][lk + 2][r] = a4.z;
        As[0][lk + 3][r] = a4.w;
        const float4 b4 = *reinterpret_cast<const float4*>(&Bb[(size_t)r * DD + lk]);
        Bs[0][lk + 0][r] = b4.x;
        Bs[0][lk + 1][r] = b4.y;
        Bs[0][lk + 2][r] = b4.z;
        Bs[0][lk + 3][r] = b4.w;
    }
    __syncthreads();

    int s = 0;
#pragma unroll 1
    for (int t = 0; t < NKT; t++) {
        // ---- prefetch next tile into registers (overlaps with compute) ----
        float4 pa[2], pb[2];
        const bool have_next = (t + 1 < NKT);
        if (have_next) {
            const int kt = (t + 1) * BK;
#pragma unroll
            for (int pass = 0; pass < 2; pass++) {
                const int r = lr + pass * 64;
                pa[pass] = *reinterpret_cast<const float4*>(&Ab[(size_t)r * DD + kt + lk]);
                pb[pass] = *reinterpret_cast<const float4*>(&Bb[(size_t)r * DD + kt + lk]);
            }
        }

        // ---- compute from buffer s ----
#pragma unroll
        for (int kk = 0; kk < BK; kk++) {
            const ulonglong2 a01 = *reinterpret_cast<const ulonglong2*>(&As[s][kk][tr]);
            const ulonglong2 a23 = *reinterpret_cast<const ulonglong2*>(&As[s][kk][tr + 4]);
            const float4 b0 = *reinterpret_cast<const float4*>(&Bs[s][kk][tc]);
            const float4 b1 = *reinterpret_cast<const float4*>(&Bs[s][kk][tc + 4]);
            const float bv[8] = {b0.x, b0.y, b0.z, b0.w, b1.x, b1.y, b1.z, b1.w};
#pragma unroll
            for (int c = 0; c < 8; c++) {
                const ull bb = splat2(bv[c]);
                fma2(acc[0][c], a01.x, bb);
                fma2(acc[1][c], a01.y, bb);
                fma2(acc[2][c], a23.x, bb);
                fma2(acc[3][c], a23.y, bb);
            }
        }

        // ---- drain prefetch into the other buffer ----
        if (have_next) {
            const int sn = s ^ 1;
#pragma unroll
            for (int pass = 0; pass < 2; pass++) {
                const int r = lr + pass * 64;
                As[sn][lk + 0][r] = pa[pass].x;
                As[sn][lk + 1][r] = pa[pass].y;
                As[sn][lk + 2][r] = pa[pass].z;
                As[sn][lk + 3][r] = pa[pass].w;
                Bs[sn][lk + 0][r] = pb[pass].x;
                Bs[sn][lk + 1][r] = pb[pass].y;
                Bs[sn][lk + 2][r] = pb[pass].z;
                Bs[sn][lk + 3][r] = pb[pass].w;
            }
            __syncthreads();
            s = sn;
        }
    }

    // ---- epilogue: unpack and store ----
#pragma unroll
    for (int rp = 0; rp < 4; rp++) {
#pragma unroll
        for (int h = 0; h < 2; h++) {
            const int r = m0 + tr + 2 * rp + h;
            float4 o0, o1;
            if (h == 0) {
                o0 = make_float4(lo32(acc[rp][0]), lo32(acc[rp][1]), lo32(acc[rp][2]), lo32(acc[rp][3]));
                o1 = make_float4(lo32(acc[rp][4]), lo32(acc[rp][5]), lo32(acc[rp][6]), lo32(acc[rp][7]));
            } else {
                o0 = make_float4(hi32(acc[rp][0]), hi32(acc[rp][1]), hi32(acc[rp][2]), hi32(acc[rp][3]));
                o1 = make_float4(hi32(acc[rp][4]), hi32(acc[rp][5]), hi32(acc[rp][6]), hi32(acc[rp][7]));
            }
            float4* dst = reinterpret_cast<float4*>(&Cb[(size_t)r * LE + n0 + tc]);
            dst[0] = o0;
            dst[1] = o1;
        }
    }
}

// In-place row softmax over LE=2048 columns. One block per row, 256 threads,
// 8 elements per thread (two float4s), kept in registers across both passes.
__global__ __launch_bounds__(256)
void softmax_rows_kernel(float* __restrict__ C)
{
    __shared__ float red[32];

    float* p = C + (size_t)blockIdx.x * LE;
    const int tid  = threadIdx.x;
    const int lane = tid & 31;
    const int wid  = tid >> 5;

    float4 v0 = *reinterpret_cast<const float4*>(&p[tid * 8]);
    float4 v1 = *reinterpret_cast<const float4*>(&p[tid * 8 + 4]);

    // ---- max reduce ----
    float m = fmaxf(fmaxf(fmaxf(v0.x, v0.y), fmaxf(v0.z, v0.w)),
                    fmaxf(fmaxf(v1.x, v1.y), fmaxf(v1.z, v1.w)));
#pragma unroll
    for (int o = 16; o > 0; o >>= 1) m = fmaxf(m, __shfl_xor_sync(0xffffffffu, m, o));
    if (lane == 0) red[wid] = m;
    __syncthreads();
    float M = red[0];
#pragma unroll
    for (int i = 1; i < 8; i++) M = fmaxf(M, red[i]);
    __syncthreads();

    // ---- exp + sum reduce ----
    v0.x = __expf(v0.x - M); v0.y = __expf(v0.y - M);
    v0.z = __expf(v0.z - M); v0.w = __expf(v0.w - M);
    v1.x = __expf(v1.x - M); v1.y = __expf(v1.y - M);
    v1.z = __expf(v1.z - M); v1.w = __expf(v1.w - M);

    float s = (v0.x + v0.y + v0.z + v0.w) + (v1.x + v1.y + v1.z + v1.w);
#pragma unroll
    for (int o = 16; o > 0; o >>= 1) s += __shfl_xor_sync(0xffffffffu, s, o);
    if (lane == 0) red[wid] = s;
    __syncthreads();
    float S = 0.f;
#pragma unroll
    for (int i = 0; i < 8; i++) S += red[i];
    const float inv = 1.0f / S;

    v0.x *= inv; v0.y *= inv; v0.z *= inv; v0.w *= inv;
    v1.x *= inv; v1.y *= inv; v1.z *= inv; v1.w *= inv;

    *reinterpret_cast<float4*>(&p[tid * 8])     = v0;
    *reinterpret_cast<float4*>(&p[tid * 8 + 4]) = v1;
}

extern "C" void kernel_launch(void* const* d_in, const int* in_sizes, int n_in,
                              void* d_out, int out_size)
{
    const float* dec = (const float*)d_in[0];   // [B, LD, DD]
    const float* enc = (const float*)d_in[1];   // [B, LE, DD]
    float* out = (float*)d_out;                 // [B, LD, LE]

    const int B = in_sizes[0] / (LD * DD);      // = 32

    dim3 grid(LE / BN, LD / BM, B);             // (16, 4, 32)
    gemm_nt_kernel<<<grid, 256>>>(dec, enc, out);

    softmax_rows_kernel<<<B * LD, 256>>>(out);
}

// round 5
// speedup vs baseline: 1.1404x; 1.1404x over previous
#include <cuda_runtime.h>
#include <cstdint>

// Problem constants (fixed by reference setup_inputs).
#define LD 512      // decoder length (M total)
#define LE 2048     // encoder length (N total)
#define DD 512      // feature dim (K)

// GEMM tiling: block 128x128, BK=32. 8 warps in 2(m) x 4(n); warp tile 64x32.
#define BM 128
#define BN 128
#define BK 32
#define NKT (DD / BK)      // 16 k-tiles
#define ROWPAD 36          // floats per smem row (pad 32 -> 36: conflict-free frag reads)
#define MAT_FLOATS (128 * ROWPAD)             // 4608 floats per matrix tile
#define STAGE_FLOATS (4 * MAT_FLOATS)         // Ah, Al, Bh, Bl
#define SMEM_FLOATS (2 * STAGE_FLOATS)        // double buffer
#define SMEM_BYTES (SMEM_FLOATS * 4)          // 147456 B

// offsets within a stage (floats)
#define OFF_AH 0
#define OFF_AL (1 * MAT_FLOATS)
#define OFF_BH (2 * MAT_FLOATS)
#define OFF_BL (3 * MAT_FLOATS)

__device__ __forceinline__ uint32_t f2tf32(float x) {
    uint32_t r;
    asm("cvt.rna.tf32.f32 %0, %1;" : "=r"(r) : "f"(x));
    return r;
}

// acc(16x8) += A(16x8 tf32, row) * B(8x8 tf32, col)
__device__ __forceinline__ void mma_tf32(float* d, const uint32_t* a, uint32_t b0, uint32_t b1) {
    asm volatile(
        "mma.sync.aligned.m16n8k8.row.col.f32.tf32.tf32.f32 "
        "{%0,%1,%2,%3}, {%4,%5,%6,%7}, {%8,%9}, {%0,%1,%2,%3};"
        : "+f"(d[0]), "+f"(d[1]), "+f"(d[2]), "+f"(d[3])
        : "r"(a[0]), "r"(a[1]), "r"(a[2]), "r"(a[3]), "r"(b0), "r"(b1));
}

// Convert one float4 (4 consecutive k of one row) into hi/lo tf32 and store to smem.
__device__ __forceinline__ void cvt_store(float* __restrict__ smh, float* __restrict__ sml,
                                          int idx, float4 v) {
    uint32_t h0 = f2tf32(v.x), h1 = f2tf32(v.y), h2 = f2tf32(v.z), h3 = f2tf32(v.w);
    uint32_t l0 = f2tf32(v.x - __uint_as_float(h0));
    uint32_t l1 = f2tf32(v.y - __uint_as_float(h1));
    uint32_t l2 = f2tf32(v.z - __uint_as_float(h2));
    uint32_t l3 = f2tf32(v.w - __uint_as_float(h3));
    *reinterpret_cast<uint4*>(smh + idx) = make_uint4(h0, h1, h2, h3);
    *reinterpret_cast<uint4*>(sml + idx) = make_uint4(l0, l1, l2, l3);
}

// scores[b, m, n] = sum_k dec[b, m, k] * enc[b, n, k]  via 3xTF32 mma.sync.
__global__ __launch_bounds__(256, 1)
void gemm_tf32_kernel(const float* __restrict__ A,   // [B, LD, DD]
                      const float* __restrict__ Bm,  // [B, LE, DD]
                      float* __restrict__ C)         // [B, LD, LE]
{
    extern __shared__ float sm[];

    const int tid = threadIdx.x;       // 256 threads
    const int b  = blockIdx.z;
    const int m0 = blockIdx.y * BM;
    const int n0 = blockIdx.x * BN;

    const float* Ab = A  + (size_t)b * LD * DD + (size_t)m0 * DD;
    const float* Bb = Bm + (size_t)b * LE * DD + (size_t)n0 * DD;
    float*       Cb = C  + (size_t)b * LD * LE;

    // ---- loader mapping: row = tid>>1 (0..127), k-half = (tid&1)*16, 4 float4s each ----
    const int lrow  = tid >> 1;
    const int lkoff = (tid & 1) * 16;
    const float* aptr = Ab + (size_t)lrow * DD + lkoff;
    const float* bptr = Bb + (size_t)lrow * DD + lkoff;
    const int sidx0 = lrow * ROWPAD + lkoff;     // smem float index base (k-tile-local)

    // ---- compute mapping ----
    const int w    = tid >> 5;
    const int lane = tid & 31;
    const int wm   = w >> 2;          // 0..1 -> 64-row slab
    const int wn   = w & 3;           // 0..3 -> 32-col slab
    const int g    = lane >> 2;       // 0..7
    const int tg   = lane & 3;        // 0..3
    const int mwb  = wm * 64;
    const int nwb  = wn * 32;

    float acc[4][4][4];
#pragma unroll
    for (int mi = 0; mi < 4; mi++)
#pragma unroll
        for (int ni = 0; ni < 4; ni++)
#pragma unroll
            for (int r = 0; r < 4; r++) acc[mi][ni][r] = 0.f;

    float4 pa[4], pb[4];

    // ---- prologue: tile 0 -> stage 0; prefetch tile 1 ----
#pragma unroll
    for (int q = 0; q < 4; q++) {
        pa[q] = *reinterpret_cast<const float4*>(aptr + q * 4);
        pb[q] = *reinterpret_cast<const float4*>(bptr + q * 4);
    }
#pragma unroll
    for (int q = 0; q < 4; q++) {
        cvt_store(sm + OFF_AH, sm + OFF_AL, sidx0 + q * 4, pa[q]);
        cvt_store(sm + OFF_BH, sm + OFF_BL, sidx0 + q * 4, pb[q]);
    }
#pragma unroll
    for (int q = 0; q < 4; q++) {
        pa[q] = *reinterpret_cast<const float4*>(aptr + BK + q * 4);
        pb[q] = *reinterpret_cast<const float4*>(bptr + BK + q * 4);
    }
    __syncthreads();

#pragma unroll 1
    for (int t = 0; t < NKT; t++) {
        float* stage  = sm + (t & 1) * STAGE_FLOATS;

        // ---- 1) drain prefetched tile t+1 into the other stage (overlaps MMAs below) ----
        if (t + 1 < NKT) {
            float* nstage = sm + ((t + 1) & 1) * STAGE_FLOATS;
#pragma unroll
            for (int q = 0; q < 4; q++) {
                cvt_store(nstage + OFF_AH, nstage + OFF_AL, sidx0 + q * 4, pa[q]);
                cvt_store(nstage + OFF_BH, nstage + OFF_BL, sidx0 + q * 4, pb[q]);
            }
        }
        // ---- 2) prefetch tile t+2 into registers ----
        if (t + 2 < NKT) {
            const int kt = (t + 2) * BK;
#pragma unroll
            for (int q = 0; q < 4; q++) {
                pa[q] = *reinterpret_cast<const float4*>(aptr + kt + q * 4);
                pb[q] = *reinterpret_cast<const float4*>(bptr + kt + q * 4);
            }
        }

        // ---- 3) compute tile t from 'stage' ----
        const float* Ah = stage + OFF_AH;
        const float* Al = stage + OFF_AL;
        const float* Bh = stage + OFF_BH;
        const float* Bl = stage + OFF_BL;

#pragma unroll
        for (int j = 0; j < 4; j++) {
            const int kb = j * 8;
            uint32_t af[4][4];
            // load Ah fragments (reused by passes hh and hl)
#pragma unroll
            for (int mi = 0; mi < 4; mi++) {
                const int r0 = (mwb + mi * 16 + g) * ROWPAD + kb + tg;
                af[mi][0] = __float_as_uint(Ah[r0]);
                af[mi][1] = __float_as_uint(Ah[r0 + 8 * ROWPAD]);
                af[mi][2] = __float_as_uint(Ah[r0 + 4]);
                af[mi][3] = __float_as_uint(Ah[r0 + 8 * ROWPAD + 4]);
            }
            // pass 1: Ah * Bh
#pragma unroll
            for (int ni = 0; ni < 4; ni++) {
                const int nb = (nwb + ni * 8 + g) * ROWPAD + kb + tg;
                const uint32_t b0 = __float_as_uint(Bh[nb]);
                const uint32_t b1 = __float_as_uint(Bh[nb + 4]);
#pragma unroll
                for (int mi = 0; mi < 4; mi++) mma_tf32(acc[mi][ni], af[mi], b0, b1);
            }
            // pass 2: Ah * Bl
#pragma unroll
            for (int ni = 0; ni < 4; ni++) {
                const int nb = (nwb + ni * 8 + g) * ROWPAD + kb + tg;
                const uint32_t b0 = __float_as_uint(Bl[nb]);
                const uint32_t b1 = __float_as_uint(Bl[nb + 4]);
#pragma unroll
                for (int mi = 0; mi < 4; mi++) mma_tf32(acc[mi][ni], af[mi], b0, b1);
            }
            // load Al fragments
#pragma unroll
            for (int mi = 0; mi < 4; mi++) {
                const int r0 = (mwb + mi * 16 + g) * ROWPAD + kb + tg;
                af[mi][0] = __float_as_uint(Al[r0]);
                af[mi][1] = __float_as_uint(Al[r0 + 8 * ROWPAD]);
                af[mi][2] = __float_as_uint(Al[r0 + 4]);
                af[mi][3] = __float_as_uint(Al[r0 + 8 * ROWPAD + 4]);
            }
            // pass 3: Al * Bh
#pragma unroll
            for (int ni = 0; ni < 4; ni++) {
                const int nb = (nwb + ni * 8 + g) * ROWPAD + kb + tg;
                const uint32_t b0 = __float_as_uint(Bh[nb]);
                const uint32_t b1 = __float_as_uint(Bh[nb + 4]);
#pragma unroll
                for (int mi = 0; mi < 4; mi++) mma_tf32(acc[mi][ni], af[mi], b0, b1);
            }
        }

        if (t + 1 < NKT) __syncthreads();
    }

    // ---- epilogue: c0:(g,2tg) c1:(g,2tg+1) c2:(g+8,2tg) c3:(g+8,2tg+1) ----
#pragma unroll
    for (int mi = 0; mi < 4; mi++) {
        const int mrow = m0 + mwb + mi * 16 + g;
#pragma unroll
        for (int ni = 0; ni < 4; ni++) {
            const int ncol = n0 + nwb + ni * 8 + 2 * tg;
            *reinterpret_cast<float2*>(&Cb[(size_t)mrow * LE + ncol]) =
                make_float2(acc[mi][ni][0], acc[mi][ni][1]);
            *reinterpret_cast<float2*>(&Cb[(size_t)(mrow + 8) * LE + ncol]) =
                make_float2(acc[mi][ni][2], acc[mi][ni][3]);
        }
    }
}

// In-place row softmax over LE=2048 columns. One block per row, 256 threads.
__global__ __launch_bounds__(256)
void softmax_rows_kernel(float* __restrict__ C)
{
    __shared__ float red[32];

    float* p = C + (size_t)blockIdx.x * LE;
    const int tid  = threadIdx.x;
    const int lane = tid & 31;
    const int wid  = tid >> 5;

    float4 v0 = *reinterpret_cast<const float4*>(&p[tid * 8]);
    float4 v1 = *reinterpret_cast<const float4*>(&p[tid * 8 + 4]);

    float m = fmaxf(fmaxf(fmaxf(v0.x, v0.y), fmaxf(v0.z, v0.w)),
                    fmaxf(fmaxf(v1.x, v1.y), fmaxf(v1.z, v1.w)));
#pragma unroll
    for (int o = 16; o > 0; o >>= 1) m = fmaxf(m, __shfl_xor_sync(0xffffffffu, m, o));
    if (lane == 0) red[wid] = m;
    __syncthreads();
    float M = red[0];
#pragma unroll
    for (int i = 1; i < 8; i++) M = fmaxf(M, red[i]);
    __syncthreads();

    v0.x = __expf(v0.x - M); v0.y = __expf(v0.y - M);
    v0.z = __expf(v0.z - M); v0.w = __expf(v0.w - M);
    v1.x = __expf(v1.x - M); v1.y = __expf(v1.y - M);
    v1.z = __expf(v1.z - M); v1.w = __expf(v1.w - M);

    float s = (v0.x + v0.y + v0.z + v0.w) + (v1.x + v1.y + v1.z + v1.w);
#pragma unroll
    for (int o = 16; o > 0; o >>= 1) s += __shfl_xor_sync(0xffffffffu, s, o);
    if (lane == 0) red[wid] = s;
    __syncthreads();
    float S = 0.f;
#pragma unroll
    for (int i = 0; i < 8; i++) S += red[i];
    const float inv = 1.0f / S;

    v0.x *= inv; v0.y *= inv; v0.z *= inv; v0.w *= inv;
    v1.x *= inv; v1.y *= inv; v1.z *= inv; v1.w *= inv;

    *reinterpret_cast<float4*>(&p[tid * 8])     = v0;
    *reinterpret_cast<float4*>(&p[tid * 8 + 4]) = v1;
}

extern "C" void kernel_launch(void* const* d_in, const int* in_sizes, int n_in,
                              void* d_out, int out_size)
{
    const float* dec = (const float*)d_in[0];   // [B, LD, DD]
    const float* enc = (const float*)d_in[1];   // [B, LE, DD]
    float* out = (float*)d_out;                 // [B, LD, LE]

    const int B = in_sizes[0] / (LD * DD);      // = 32

    cudaFuncSetAttribute(gemm_tf32_kernel,
                         cudaFuncAttributeMaxDynamicSharedMemorySize, SMEM_BYTES);

    dim3 grid(LE / BN, LD / BM, B);             // (16, 4, 32) = 2048 CTAs
    gemm_tf32_kernel<<<grid, 256, SMEM_BYTES>>>(dec, enc, out);

    softmax_rows_kernel<<<B * LD, 256>>>(out);
}

// round 6
// speedup vs baseline: 1.5406x; 1.3510x over previous
#include <cuda_runtime.h>
#include <cuda_fp16.h>
#include <cstdint>

// Problem constants (fixed by reference setup_inputs).
#define LD 512      // decoder length (M total)
#define LE 2048     // encoder length (N total)
#define DD 512      // feature dim (K)

// GEMM tiling: block 128x128, BK=32. 8 warps in 2(m) x 4(n); warp tile 64x32.
#define BM 128
#define BN 128
#define BK 32
#define NKT (DD / BK)      // 16 k-tiles

// smem rows hold 32 fp16 = 16 b32, padded to 20 b32 (stride-20 pattern is
// conflict-free for the (g, tg) fragment loads: g*20+tg covers 32 distinct banks).
#define RSTRIDE 20
#define MAT_U32 (128 * RSTRIDE)            // 2560 b32 per matrix tile
#define STAGE_U32 (4 * MAT_U32)            // Ah, Al, Bh, Bl
#define SMEM_BYTES (2 * STAGE_U32 * 4)     // 81920 B (double buffered)

// offsets within a stage (b32 units)
#define OFF_AH 0
#define OFF_AL (1 * MAT_U32)
#define OFF_BH (2 * MAT_U32)
#define OFF_BL (3 * MAT_U32)

__device__ __forceinline__ uint32_t pack2(__half a, __half b) {
    return (uint32_t)__half_as_ushort(a) | ((uint32_t)__half_as_ushort(b) << 16);
}

// acc(16x8) += A(16x16 f16, row) * B(16x8 f16, col), fp32 accumulate
__device__ __forceinline__ void mma_f16(float* d, const uint32_t* a, uint32_t b0, uint32_t b1) {
    asm volatile(
        "mma.sync.aligned.m16n8k16.row.col.f32.f16.f16.f32 "
        "{%0,%1,%2,%3}, {%4,%5,%6,%7}, {%8,%9}, {%0,%1,%2,%3};"
        : "+f"(d[0]), "+f"(d[1]), "+f"(d[2]), "+f"(d[3])
        : "r"(a[0]), "r"(a[1]), "r"(a[2]), "r"(a[3]), "r"(b0), "r"(b1));
}

// Convert one float4 (4 consecutive k of one row) into hi/lo fp16 pairs and store.
__device__ __forceinline__ void cvt_store(uint32_t* __restrict__ smh, uint32_t* __restrict__ sml,
                                          int idx, float4 v) {
    const __half hx = __float2half_rn(v.x), hy = __float2half_rn(v.y);
    const __half hz = __float2half_rn(v.z), hw = __float2half_rn(v.w);
    const __half lx = __float2half_rn(v.x - __half2float(hx));
    const __half ly = __float2half_rn(v.y - __half2float(hy));
    const __half lz = __float2half_rn(v.z - __half2float(hz));
    const __half lw = __float2half_rn(v.w - __half2float(hw));
    *reinterpret_cast<uint2*>(smh + idx) = make_uint2(pack2(hx, hy), pack2(hz, hw));
    *reinterpret_cast<uint2*>(sml + idx) = make_uint2(pack2(lx, ly), pack2(lz, lw));
}

// scores[b, m, n] = sum_k dec[b, m, k] * enc[b, n, k]  via 3xFP16 mma.sync.
__global__ __launch_bounds__(256, 1)
void gemm_f16x3_kernel(const float* __restrict__ A,   // [B, LD, DD]
                       const float* __restrict__ Bm,  // [B, LE, DD]
                       float* __restrict__ C)         // [B, LD, LE]
{
    extern __shared__ uint32_t sm[];

    const int tid = threadIdx.x;       // 256 threads
    const int b  = blockIdx.z;
    const int m0 = blockIdx.y * BM;
    const int n0 = blockIdx.x * BN;

    const float* Ab = A  + (size_t)b * LD * DD + (size_t)m0 * DD;
    const float* Bb = Bm + (size_t)b * LE * DD + (size_t)n0 * DD;
    float*       Cb = C  + (size_t)b * LD * LE;

    // ---- loader mapping: row = tid>>1 (0..127), k-half = (tid&1)*16 floats ----
    const int lrow  = tid >> 1;
    const int lkoff = (tid & 1) * 16;              // float offset
    const float* aptr = Ab + (size_t)lrow * DD + lkoff;
    const float* bptr = Bb + (size_t)lrow * DD + lkoff;
    const int sidx0 = lrow * RSTRIDE + lkoff / 2;  // b32 index base within tile

    // ---- compute mapping ----
    const int w    = tid >> 5;
    const int lane = tid & 31;
    const int wm   = w >> 2;          // 0..1 -> 64-row slab
    const int wn   = w & 3;           // 0..3 -> 32-col slab
    const int g    = lane >> 2;       // 0..7
    const int tg   = lane & 3;        // 0..3
    const int mwb  = wm * 64;
    const int nwb  = wn * 32;

    float acc[4][4][4];
#pragma unroll
    for (int mi = 0; mi < 4; mi++)
#pragma unroll
        for (int ni = 0; ni < 4; ni++)
#pragma unroll
            for (int r = 0; r < 4; r++) acc[mi][ni][r] = 0.f;

    float4 pa[4], pb[4];

    // ---- prologue: tile 0 -> stage 0; prefetch tile 1 ----
#pragma unroll
    for (int q = 0; q < 4; q++) {
        pa[q] = *reinterpret_cast<const float4*>(aptr + q * 4);
        pb[q] = *reinterpret_cast<const float4*>(bptr + q * 4);
    }
#pragma unroll
    for (int q = 0; q < 4; q++) {
        cvt_store(sm + OFF_AH, sm + OFF_AL, sidx0 + q * 2, pa[q]);
        cvt_store(sm + OFF_BH, sm + OFF_BL, sidx0 + q * 2, pb[q]);
    }
#pragma unroll
    for (int q = 0; q < 4; q++) {
        pa[q] = *reinterpret_cast<const float4*>(aptr + BK + q * 4);
        pb[q] = *reinterpret_cast<const float4*>(bptr + BK + q * 4);
    }
    __syncthreads();

#pragma unroll 1
    for (int t = 0; t < NKT; t++) {
        uint32_t* stage = sm + (t & 1) * STAGE_U32;

        // ---- 1) drain prefetched tile t+1 into the other stage (overlaps MMAs) ----
        if (t + 1 < NKT) {
            uint32_t* nstage = sm + ((t + 1) & 1) * STAGE_U32;
#pragma unroll
            for (int q = 0; q < 4; q++) {
                cvt_store(nstage + OFF_AH, nstage + OFF_AL, sidx0 + q * 2, pa[q]);
                cvt_store(nstage + OFF_BH, nstage + OFF_BL, sidx0 + q * 2, pb[q]);
            }
        }
        // ---- 2) prefetch tile t+2 into registers ----
        if (t + 2 < NKT) {
            const int kt = (t + 2) * BK;
#pragma unroll
            for (int q = 0; q < 4; q++) {
                pa[q] = *reinterpret_cast<const float4*>(aptr + kt + q * 4);
                pb[q] = *reinterpret_cast<const float4*>(bptr + kt + q * 4);
            }
        }

        // ---- 3) compute tile t ----
        const uint32_t* Ah = stage + OFF_AH;
        const uint32_t* Al = stage + OFF_AL;
        const uint32_t* Bh = stage + OFF_BH;
        const uint32_t* Bl = stage + OFF_BL;

#pragma unroll
        for (int ks = 0; ks < 2; ks++) {
            const int kb = ks * 8;           // b32 offset of this k16 step
            uint32_t af[4][4];
            uint32_t bh[4][2], bl[4][2];
#pragma unroll
            for (int ni = 0; ni < 4; ni++) {
                const int nb = (nwb + ni * 8 + g) * RSTRIDE + kb + tg;
                bh[ni][0] = Bh[nb]; bh[ni][1] = Bh[nb + 4];
                bl[ni][0] = Bl[nb]; bl[ni][1] = Bl[nb + 4];
            }
            // Ah fragments (reused by passes hh and hl)
#pragma unroll
            for (int mi = 0; mi < 4; mi++) {
                const int r0 = (mwb + mi * 16 + g) * RSTRIDE + kb + tg;
                af[mi][0] = Ah[r0];
                af[mi][1] = Ah[r0 + 8 * RSTRIDE];
                af[mi][2] = Ah[r0 + 4];
                af[mi][3] = Ah[r0 + 8 * RSTRIDE + 4];
            }
#pragma unroll
            for (int ni = 0; ni < 4; ni++)        // pass 1: Ah * Bh
#pragma unroll
                for (int mi = 0; mi < 4; mi++) mma_f16(acc[mi][ni], af[mi], bh[ni][0], bh[ni][1]);
#pragma unroll
            for (int ni = 0; ni < 4; ni++)        // pass 2: Ah * Bl
#pragma unroll
                for (int mi = 0; mi < 4; mi++) mma_f16(acc[mi][ni], af[mi], bl[ni][0], bl[ni][1]);
            // Al fragments
#pragma unroll
            for (int mi = 0; mi < 4; mi++) {
                const int r0 = (mwb + mi * 16 + g) * RSTRIDE + kb + tg;
                af[mi][0] = Al[r0];
                af[mi][1] = Al[r0 + 8 * RSTRIDE];
                af[mi][2] = Al[r0 + 4];
                af[mi][3] = Al[r0 + 8 * RSTRIDE + 4];
            }
#pragma unroll
            for (int ni = 0; ni < 4; ni++)        // pass 3: Al * Bh
#pragma unroll
                for (int mi = 0; mi < 4; mi++) mma_f16(acc[mi][ni], af[mi], bh[ni][0], bh[ni][1]);
        }

        if (t + 1 < NKT) __syncthreads();
    }

    // ---- epilogue: c0:(g,2tg) c1:(g,2tg+1) c2:(g+8,2tg) c3:(g+8,2tg+1) ----
#pragma unroll
    for (int mi = 0; mi < 4; mi++) {
        const int mrow = m0 + mwb + mi * 16 + g;
#pragma unroll
        for (int ni = 0; ni < 4; ni++) {
            const int ncol = n0 + nwb + ni * 8 + 2 * tg;
            *reinterpret_cast<float2*>(&Cb[(size_t)mrow * LE + ncol]) =
                make_float2(acc[mi][ni][0], acc[mi][ni][1]);
            *reinterpret_cast<float2*>(&Cb[(size_t)(mrow + 8) * LE + ncol]) =
                make_float2(acc[mi][ni][2], acc[mi][ni][3]);
        }
    }
}

// In-place row softmax over LE=2048 columns. One block per row, 256 threads.
__global__ __launch_bounds__(256)
void softmax_rows_kernel(float* __restrict__ C)
{
    __shared__ float red[32];

    float* p = C + (size_t)blockIdx.x * LE;
    const int tid  = threadIdx.x;
    const int lane = tid & 31;
    const int wid  = tid >> 5;

    float4 v0 = *reinterpret_cast<const float4*>(&p[tid * 8]);
    float4 v1 = *reinterpret_cast<const float4*>(&p[tid * 8 + 4]);

    float m = fmaxf(fmaxf(fmaxf(v0.x, v0.y), fmaxf(v0.z, v0.w)),
                    fmaxf(fmaxf(v1.x, v1.y), fmaxf(v1.z, v1.w)));
#pragma unroll
    for (int o = 16; o > 0; o >>= 1) m = fmaxf(m, __shfl_xor_sync(0xffffffffu, m, o));
    if (lane == 0) red[wid] = m;
    __syncthreads();
    float M = red[0];
#pragma unroll
    for (int i = 1; i < 8; i++) M = fmaxf(M, red[i]);
    __syncthreads();

    v0.x = __expf(v0.x - M); v0.y = __expf(v0.y - M);
    v0.z = __expf(v0.z - M); v0.w = __expf(v0.w - M);
    v1.x = __expf(v1.x - M); v1.y = __expf(v1.y - M);
    v1.z = __expf(v1.z - M); v1.w = __expf(v1.w - M);

    float s = (v0.x + v0.y + v0.z + v0.w) + (v1.x + v1.y + v1.z + v1.w);
#pragma unroll
    for (int o = 16; o > 0; o >>= 1) s += __shfl_xor_sync(0xffffffffu, s, o);
    if (lane == 0) red[wid] = s;
    __syncthreads();
    float S = 0.f;
#pragma unroll
    for (int i = 0; i < 8; i++) S += red[i];
    const float inv = 1.0f / S;

    v0.x *= inv; v0.y *= inv; v0.z *= inv; v0.w *= inv;
    v1.x *= inv; v1.y *= inv; v1.z *= inv; v1.w *= inv;

    *reinterpret_cast<float4*>(&p[tid * 8])     = v0;
    *reinterpret_cast<float4*>(&p[tid * 8 + 4]) = v1;
}

extern "C" void kernel_launch(void* const* d_in, const int* in_sizes, int n_in,
                              void* d_out, int out_size)
{
    const float* dec = (const float*)d_in[0];   // [B, LD, DD]
    const float* enc = (const float*)d_in[1];   // [B, LE, DD]
    float* out = (float*)d_out;                 // [B, LD, LE]

    const int B = in_sizes[0] / (LD * DD);      // = 32

    cudaFuncSetAttribute(gemm_f16x3_kernel,
                         cudaFuncAttributeMaxDynamicSharedMemorySize, SMEM_BYTES);

    dim3 grid(LE / BN, LD / BM, B);             // (16, 4, 32) = 2048 CTAs
    gemm_f16x3_kernel<<<grid, 256, SMEM_BYTES>>>(dec, enc, out);

    softmax_rows_kernel<<<B * LD, 256>>>(out);
}

// round 9
// speedup vs baseline: 1.7966x; 1.1661x over previous
#include <cuda_runtime.h>
#include <cuda_fp16.h>
#include <cstdint>

// Problem constants (fixed by reference setup_inputs).
#define LD 512      // decoder length (M total)
#define LE 2048     // encoder length (N total)
#define DD 512      // feature dim (K)

// GEMM tiling: block 128x128, BK=32. 8 warps in 2(m) x 4(n); warp tile 64x32.
// SINGLE-buffered 40KB stage -> static smem, occupancy 2 -> cross-CTA overlap.
#define BM 128
#define BN 128
#define BK 32
#define NKT (DD / BK)      // 16 k-tiles

// smem rows hold 32 fp16 = 16 b32, padded to 20 b32 (stride-20 pattern is
// conflict-free for the (g, tg) fragment loads).
#define RSTRIDE 20
#define MAT_U32 (128 * RSTRIDE)            // 2560 b32 per matrix tile

// offsets within the stage (b32 units)
#define OFF_AH 0
#define OFF_AL (1 * MAT_U32)
#define OFF_BH (2 * MAT_U32)
#define OFF_BL (3 * MAT_U32)
#define STAGE_U32 (4 * MAT_U32)            // 10240 b32 = 40960 B

__device__ __forceinline__ uint32_t pack2(__half a, __half b) {
    return (uint32_t)__half_as_ushort(a) | ((uint32_t)__half_as_ushort(b) << 16);
}

// acc(16x8) += A(16x16 f16, row) * B(16x8 f16, col), fp32 accumulate
__device__ __forceinline__ void mma_f16(float* d, const uint32_t* a, uint32_t b0, uint32_t b1) {
    asm volatile(
        "mma.sync.aligned.m16n8k16.row.col.f32.f16.f16.f32 "
        "{%0,%1,%2,%3}, {%4,%5,%6,%7}, {%8,%9}, {%0,%1,%2,%3};"
        : "+f"(d[0]), "+f"(d[1]), "+f"(d[2]), "+f"(d[3])
        : "r"(a[0]), "r"(a[1]), "r"(a[2]), "r"(a[3]), "r"(b0), "r"(b1));
}

// Convert one float4 (4 consecutive k of one row) into hi/lo fp16 pairs and store.
__device__ __forceinline__ void cvt_store(uint32_t* __restrict__ smh, uint32_t* __restrict__ sml,
                                          int idx, float4 v) {
    const __half hx = __float2half_rn(v.x), hy = __float2half_rn(v.y);
    const __half hz = __float2half_rn(v.z), hw = __float2half_rn(v.w);
    const __half lx = __float2half_rn(v.x - __half2float(hx));
    const __half ly = __float2half_rn(v.y - __half2float(hy));
    const __half lz = __float2half_rn(v.z - __half2float(hz));
    const __half lw = __float2half_rn(v.w - __half2float(hw));
    *reinterpret_cast<uint2*>(smh + idx) = make_uint2(pack2(hx, hy), pack2(hz, hw));
    *reinterpret_cast<uint2*>(sml + idx) = make_uint2(pack2(lx, ly), pack2(lz, lw));
}

// scores[b, m, n] = sum_k dec[b, m, k] * enc[b, n, k]  via 3xFP16 mma.sync.
__global__ __launch_bounds__(256, 2)
void gemm_f16x3_kernel(const float* __restrict__ A,   // [B, LD, DD]
                       const float* __restrict__ Bm,  // [B, LE, DD]
                       float* __restrict__ C)         // [B, LD, LE]
{
    __shared__ uint32_t sm[STAGE_U32];

    const int tid = threadIdx.x;       // 256 threads
    const int b  = blockIdx.z;
    const int m0 = blockIdx.y * BM;
    const int n0 = blockIdx.x * BN;

    const float* Ab = A  + (size_t)b * LD * DD + (size_t)m0 * DD;
    const float* Bb = Bm + (size_t)b * LE * DD + (size_t)n0 * DD;
    float*       Cb = C  + (size_t)b * LD * LE;

    // ---- loader mapping: row = tid>>1 (0..127), k-half = (tid&1)*16 floats ----
    const int lrow  = tid >> 1;
    const int lkoff = (tid & 1) * 16;              // float offset
    const float* aptr = Ab + (size_t)lrow * DD + lkoff;
    const float* bptr = Bb + (size_t)lrow * DD + lkoff;
    const int sidx0 = lrow * RSTRIDE + lkoff / 2;  // b32 index base within tile

    // ---- compute mapping ----
    const int w    = tid >> 5;
    const int lane = tid & 31;
    const int wm   = w >> 2;          // 0..1 -> 64-row slab
    const int wn   = w & 3;           // 0..3 -> 32-col slab
    const int g    = lane >> 2;       // 0..7
    const int tg   = lane & 3;        // 0..3
    const int mwb  = wm * 64;
    const int nwb  = wn * 32;

    float acc[4][4][4];
#pragma unroll
    for (int mi = 0; mi < 4; mi++)
#pragma unroll
        for (int ni = 0; ni < 4; ni++)
#pragma unroll
            for (int r = 0; r < 4; r++) acc[mi][ni][r] = 0.f;

#pragma unroll 1
    for (int t = 0; t < NKT; t++) {
        // ---- load tile t, convert, store to smem (other CTA computes meanwhile) ----
        const int kt = t * BK;
        {
            float4 va[4], vb[4];
#pragma unroll
            for (int q = 0; q < 4; q++) {
                va[q] = *reinterpret_cast<const float4*>(aptr + kt + q * 4);
                vb[q] = *reinterpret_cast<const float4*>(bptr + kt + q * 4);
            }
#pragma unroll
            for (int q = 0; q < 4; q++) {
                cvt_store(sm + OFF_AH, sm + OFF_AL, sidx0 + q * 2, va[q]);
                cvt_store(sm + OFF_BH, sm + OFF_BL, sidx0 + q * 2, vb[q]);
            }
        }
        __syncthreads();

        // ---- compute tile t ----
        const uint32_t* Ah = sm + OFF_AH;
        const uint32_t* Al = sm + OFF_AL;
        const uint32_t* Bh = sm + OFF_BH;
        const uint32_t* Bl = sm + OFF_BL;

#pragma unroll
        for (int ks = 0; ks < 2; ks++) {
            const int kb = ks * 8;           // b32 offset of this k16 step
            uint32_t af[4][4];
            uint32_t bh[4][2], bl[4][2];
#pragma unroll
            for (int ni = 0; ni < 4; ni++) {
                const int nb = (nwb + ni * 8 + g) * RSTRIDE + kb + tg;
                bh[ni][0] = Bh[nb]; bh[ni][1] = Bh[nb + 4];
                bl[ni][0] = Bl[nb]; bl[ni][1] = Bl[nb + 4];
            }
            // Ah fragments (reused by passes hh and hl)
#pragma unroll
            for (int mi = 0; mi < 4; mi++) {
                const int r0 = (mwb + mi * 16 + g) * RSTRIDE + kb + tg;
                af[mi][0] = Ah[r0];
                af[mi][1] = Ah[r0 + 8 * RSTRIDE];
                af[mi][2] = Ah[r0 + 4];
                af[mi][3] = Ah[r0 + 8 * RSTRIDE + 4];
            }
#pragma unroll
            for (int ni = 0; ni < 4; ni++)        // pass 1: Ah * Bh
#pragma unroll
                for (int mi = 0; mi < 4; mi++) mma_f16(acc[mi][ni], af[mi], bh[ni][0], bh[ni][1]);
#pragma unroll
            for (int ni = 0; ni < 4; ni++)        // pass 2: Ah * Bl
#pragma unroll
                for (int mi = 0; mi < 4; mi++) mma_f16(acc[mi][ni], af[mi], bl[ni][0], bl[ni][1]);
            // Al fragments
#pragma unroll
            for (int mi = 0; mi < 4; mi++) {
                const int r0 = (mwb + mi * 16 + g) * RSTRIDE + kb + tg;
                af[mi][0] = Al[r0];
                af[mi][1] = Al[r0 + 8 * RSTRIDE];
                af[mi][2] = Al[r0 + 4];
                af[mi][3] = Al[r0 + 8 * RSTRIDE + 4];
            }
#pragma unroll
            for (int ni = 0; ni < 4; ni++)        // pass 3: Al * Bh
#pragma unroll
                for (int mi = 0; mi < 4; mi++) mma_f16(acc[mi][ni], af[mi], bh[ni][0], bh[ni][1]);
        }

        if (t + 1 < NKT) __syncthreads();
    }

    // ---- epilogue: c0:(g,2tg) c1:(g,2tg+1) c2:(g+8,2tg) c3:(g+8,2tg+1) ----
#pragma unroll
    for (int mi = 0; mi < 4; mi++) {
        const int mrow = m0 + mwb + mi * 16 + g;
#pragma unroll
        for (int ni = 0; ni < 4; ni++) {
            const int ncol = n0 + nwb + ni * 8 + 2 * tg;
            *reinterpret_cast<float2*>(&Cb[(size_t)mrow * LE + ncol]) =
                make_float2(acc[mi][ni][0], acc[mi][ni][1]);
            *reinterpret_cast<float2*>(&Cb[(size_t)(mrow + 8) * LE + ncol]) =
                make_float2(acc[mi][ni][2], acc[mi][ni][3]);
        }
    }
}

// In-place row softmax over LE=2048 columns. One block per row, 256 threads.
__global__ __launch_bounds__(256)
void softmax_rows_kernel(float* __restrict__ C)
{
    __shared__ float red[32];

    float* p = C + (size_t)blockIdx.x * LE;
    const int tid  = threadIdx.x;
    const int lane = tid & 31;
    const int wid  = tid >> 5;

    float4 v0 = *reinterpret_cast<const float4*>(&p[tid * 8]);
    float4 v1 = *reinterpret_cast<const float4*>(&p[tid * 8 + 4]);

    float m = fmaxf(fmaxf(fmaxf(v0.x, v0.y), fmaxf(v0.z, v0.w)),
                    fmaxf(fmaxf(v1.x, v1.y), fmaxf(v1.z, v1.w)));
#pragma unroll
    for (int o = 16; o > 0; o >>= 1) m = fmaxf(m, __shfl_xor_sync(0xffffffffu, m, o));
    if (lane == 0) red[wid] = m;
    __syncthreads();
    float M = red[0];
#pragma unroll
    for (int i = 1; i < 8; i++) M = fmaxf(M, red[i]);
    __syncthreads();

    v0.x = __expf(v0.x - M); v0.y = __expf(v0.y - M);
    v0.z = __expf(v0.z - M); v0.w = __expf(v0.w - M);
    v1.x = __expf(v1.x - M); v1.y = __expf(v1.y - M);
    v1.z = __expf(v1.z - M); v1.w = __expf(v1.w - M);

    float s = (v0.x + v0.y + v0.z + v0.w) + (v1.x + v1.y + v1.z + v1.w);
#pragma unroll
    for (int o = 16; o > 0; o >>= 1) s += __shfl_xor_sync(0xffffffffu, s, o);
    if (lane == 0) red[wid] = s;
    __syncthreads();
    float S = 0.f;
#pragma unroll
    for (int i = 0; i < 8; i++) S += red[i];
    const float inv = 1.0f / S;

    v0.x *= inv; v0.y *= inv; v0.z *= inv; v0.w *= inv;
    v1.x *= inv; v1.y *= inv; v1.z *= inv; v1.w *= inv;

    *reinterpret_cast<float4*>(&p[tid * 8])     = v0;
    *reinterpret_cast<float4*>(&p[tid * 8 + 4]) = v1;
}

extern "C" void kernel_launch(void* const* d_in, const int* in_sizes, int n_in,
                              void* d_out, int out_size)
{
    const float* dec = (const float*)d_in[0];   // [B, LD, DD]
    const float* enc = (const float*)d_in[1];   // [B, LE, DD]
    float* out = (float*)d_out;                 // [B, LD, LE]

    const int B = in_sizes[0] / (LD * DD);      // = 32

    dim3 grid(LE / BN, LD / BM, B);             // (16, 4, 32) = 2048 CTAs
    gemm_f16x3_kernel<<<grid, 256>>>(dec, enc, out);

    softmax_rows_kernel<<<B * LD, 256>>>(out);
}